// round 11
// baseline (speedup 1.0000x reference)
#include <cuda_runtime.h>
#include <cuda_bf16.h>
#include <cstdint>

#define M_DIM 8192
#define N_DIM 4096
#define K_DIM 4096

// ---------------- scratch (no allocations allowed) ----------------
__device__ float g_absmax[2];                         // [0]=x, [1]=W
__device__ __nv_bfloat16 g_qx[(size_t)M_DIM * K_DIM]; // 64 MB
__device__ __nv_bfloat16 g_qw[(size_t)N_DIM * K_DIM]; // 32 MB

// ---------------- init ----------------
__global__ void init_kernel() {
    if (threadIdx.x < 2) g_absmax[threadIdx.x] = 0.0f;
}

// ---------------- absmax reduction ----------------
__global__ void absmax_kernel(const float4* __restrict__ p, int n4, int slot) {
    float m = 0.0f;
    int stride = gridDim.x * blockDim.x;
    for (int i = blockIdx.x * blockDim.x + threadIdx.x; i < n4; i += stride) {
        float4 v = p[i];
        m = fmaxf(m, fmaxf(fmaxf(fabsf(v.x), fabsf(v.y)),
                           fmaxf(fabsf(v.z), fabsf(v.w))));
    }
    #pragma unroll
    for (int o = 16; o; o >>= 1) m = fmaxf(m, __shfl_xor_sync(0xFFFFFFFFu, m, o));
    __shared__ float sm[32];
    if ((threadIdx.x & 31) == 0) sm[threadIdx.x >> 5] = m;
    __syncthreads();
    if (threadIdx.x < 32) {
        m = (threadIdx.x < (blockDim.x >> 5)) ? sm[threadIdx.x] : 0.0f;
        #pragma unroll
        for (int o = 16; o; o >>= 1) m = fmaxf(m, __shfl_xor_sync(0xFFFFFFFFu, m, o));
        if (threadIdx.x == 0)
            atomicMax((unsigned int*)&g_absmax[slot], __float_as_uint(m));
    }
}

// ---------------- quantize to integer-valued bf16 (8 elems/thread) ----------------
__device__ __forceinline__ uint32_t qpack2(float a, float b, float s, float lo) {
    float q0 = fminf(fmaxf(rintf(a / s), lo), 127.0f);
    float q1 = fminf(fmaxf(rintf(b / s), lo), 127.0f);
    __nv_bfloat162 h = __floats2bfloat162_rn(q0, q1);
    return *(uint32_t*)&h;
}

__global__ void quant_x_kernel(const float4* __restrict__ in, int n8) {
    int i = blockIdx.x * blockDim.x + threadIdx.x;
    if (i >= n8) return;
    const float s = g_absmax[0] / 127.0f;
    float4 v0 = in[i * 2 + 0];
    float4 v1 = in[i * 2 + 1];
    uint4 o;
    o.x = qpack2(v0.x, v0.y, s, -128.0f);
    o.y = qpack2(v0.z, v0.w, s, -128.0f);
    o.z = qpack2(v1.x, v1.y, s, -128.0f);
    o.w = qpack2(v1.z, v1.w, s, -128.0f);
    ((uint4*)g_qx)[i] = o;   // device-side symbol binding (round-7 lesson)
}

__global__ void quant_w_kernel(const float4* __restrict__ in, int n8) {
    int i = blockIdx.x * blockDim.x + threadIdx.x;
    if (i >= n8) return;
    const float s = g_absmax[1] / 127.0f;
    float4 v0 = in[i * 2 + 0];
    float4 v1 = in[i * 2 + 1];
    uint4 o;
    o.x = qpack2(v0.x, v0.y, s, -127.0f);
    o.y = qpack2(v0.z, v0.w, s, -127.0f);
    o.z = qpack2(v1.x, v1.y, s, -127.0f);
    o.w = qpack2(v1.z, v1.w, s, -127.0f);
    ((uint4*)g_qw)[i] = o;
}

// ---------------- GEMM: C[M,N] = qx[M,K] * qw[N,K]^T ----------------
#define BM 128
#define BN 256
#define BK 64          // 64 bf16 = 128 bytes per row
#define NTHREADS 512   // 16 warps: 2 (M) x 8 (N); 4 warps per SMSP
#define NSTAGE 4
#define KT (K_DIM / BK)            // 64
#define A_BYTES (BM * 128)         // 16 KB
#define B_BYTES (BN * 128)         // 32 KB
#define STAGE_BYTES (A_BYTES + B_BYTES)  // 48 KB
#define SMEM_DYN (NSTAGE * STAGE_BYTES + 128)  // 192 KB + pad

__device__ __forceinline__ unsigned smem_u32(const void* p) {
    return (unsigned)__cvta_generic_to_shared(p);
}

__device__ __forceinline__ void ldsm4(unsigned r[4], unsigned addr) {
    asm volatile("ldmatrix.sync.aligned.m8n8.x4.shared.b16 {%0,%1,%2,%3}, [%4];"
                 : "=r"(r[0]), "=r"(r[1]), "=r"(r[2]), "=r"(r[3])
                 : "r"(addr));
}

__device__ __forceinline__ void mma_bf16(float c[4],
                                         unsigned a0, unsigned a1, unsigned a2, unsigned a3,
                                         unsigned b0, unsigned b1) {
    asm volatile(
        "mma.sync.aligned.m16n8k16.row.col.f32.bf16.bf16.f32 "
        "{%0,%1,%2,%3}, {%4,%5,%6,%7}, {%8,%9}, {%0,%1,%2,%3};"
        : "+f"(c[0]), "+f"(c[1]), "+f"(c[2]), "+f"(c[3])
        : "r"(a0), "r"(a1), "r"(a2), "r"(a3), "r"(b0), "r"(b1));
}

__global__ __launch_bounds__(NTHREADS, 1) void gemm_kernel(float* __restrict__ C,
                                                           const float* __restrict__ bias) {
    extern __shared__ __align__(128) uint8_t dynsmem[];
    uint32_t smbase = smem_u32(dynsmem);
    smbase = (smbase + 127u) & ~127u;

    const int tid  = threadIdx.x;
    const int lane = tid & 31;
    const int warp = tid >> 5;
    const int wm   = warp >> 3;   // 0..1  (64 rows)
    const int wn   = warp & 7;    // 0..7  (32 cols)
    const int bm0  = blockIdx.y * BM;
    const int bn0  = blockIdx.x * BN;

    const __nv_bfloat16* gA = g_qx + (size_t)bm0 * K_DIM;
    const __nv_bfloat16* gB = g_qw + (size_t)bn0 * K_DIM;

    float acc[4][4][4];
    #pragma unroll
    for (int mi = 0; mi < 4; ++mi)
        #pragma unroll
        for (int ni = 0; ni < 4; ++ni)
            #pragma unroll
            for (int r = 0; r < 4; ++r) acc[mi][ni][r] = 0.0f;

    // stage loader: A = 1024 chunks (2/thread), B = 2048 chunks (4/thread)
    auto load_stage = [&](int kt, int stage) {
        const uint32_t sa = smbase + stage * STAGE_BYTES;
        const uint32_t sb = sa + A_BYTES;
        const int k0 = kt * BK;
        #pragma unroll
        for (int i = 0; i < 2; ++i) {
            const int id  = tid + i * NTHREADS;
            const int row = id >> 3, ch = id & 7;
            const uint32_t off = row * 128 + ((ch ^ (row & 7)) << 4);
            const void* src = gA + (size_t)row * K_DIM + k0 + ch * 8;
            asm volatile("cp.async.cg.shared.global [%0], [%1], 16;\n"
                         :: "r"(sa + off), "l"(src));
        }
        #pragma unroll
        for (int i = 0; i < 4; ++i) {
            const int id  = tid + i * NTHREADS;
            const int row = id >> 3, ch = id & 7;
            const uint32_t off = row * 128 + ((ch ^ (row & 7)) << 4);
            const void* src = gB + (size_t)row * K_DIM + k0 + ch * 8;
            asm volatile("cp.async.cg.shared.global [%0], [%1], 16;\n"
                         :: "r"(sb + off), "l"(src));
        }
        asm volatile("cp.async.commit_group;\n" ::: "memory");
    };

    load_stage(0, 0);
    load_stage(1, 1);
    load_stage(2, 2);

    // fragment address components
    const int arow[4] = {wm * 64 + 0 * 16 + (lane & 15), wm * 64 + 1 * 16 + (lane & 15),
                         wm * 64 + 2 * 16 + (lane & 15), wm * 64 + 3 * 16 + (lane & 15)};
    const int abit = lane >> 4;
    const int brow[2] = {wn * 32 + 0 * 16 + (lane & 7) + ((lane >> 4) << 3),
                         wn * 32 + 1 * 16 + (lane & 7) + ((lane >> 4) << 3)};
    const int bbit = (lane >> 3) & 1;

    // ring-buffered fragments: af = 2x4 regs (per-mi ring), bf = 2x2x4 (per-ks ring)
    unsigned af[2][4], bf[2][2][4];

    for (int kt = 0; kt < KT; ++kt) {
        asm volatile("cp.async.wait_group 2;\n" ::: "memory");
        __syncthreads();
        if (kt + 3 < KT) load_stage(kt + 3, (kt + 3) & 3);
        else asm volatile("cp.async.commit_group;\n" ::: "memory");

        const uint32_t sa = smbase + (kt & 3) * STAGE_BYTES;
        const uint32_t sb = sa + A_BYTES;

        // address helpers (fully static under unrolling)
        #define ADDR_A(mi, ks) (sa + arow[mi] * 128 + ((((ks) * 2 + abit) ^ (arow[mi] & 7)) << 4))
        #define ADDR_B(nj, ks) (sb + brow[nj] * 128 + ((((ks) * 2 + bbit) ^ (brow[nj] & 7)) << 4))

        // preload ks=0 fragments
        ldsm4(bf[0][0], ADDR_B(0, 0));
        ldsm4(bf[0][1], ADDR_B(1, 0));
        ldsm4(af[0],    ADDR_A(0, 0));

        #pragma unroll
        for (int ks = 0; ks < 4; ++ks) {        // BK/16
            const int cb = ks & 1;
            #pragma unroll
            for (int mi = 0; mi < 4; ++mi) {
                const int ca = mi & 1;
                // prefetch next A fragment (hidden under this mi's 4-HMMA chain)
                if (mi < 3)       ldsm4(af[ca ^ 1], ADDR_A(mi + 1, ks));
                else if (ks < 3)  ldsm4(af[ca ^ 1], ADDR_A(0, ks + 1));
                // prefetch next ks's B fragments once per ks
                if (mi == 0 && ks < 3) {
                    ldsm4(bf[cb ^ 1][0], ADDR_B(0, ks + 1));
                    ldsm4(bf[cb ^ 1][1], ADDR_B(1, ks + 1));
                }
                #pragma unroll
                for (int ni = 0; ni < 4; ++ni)
                    mma_bf16(acc[mi][ni],
                             af[ca][0], af[ca][1], af[ca][2], af[ca][3],
                             bf[cb][ni >> 1][(ni & 1) * 2], bf[cb][ni >> 1][(ni & 1) * 2 + 1]);
            }
        }
        #undef ADDR_A
        #undef ADDR_B
    }

    // epilogue: out = (4*s_x*s_w)*acc + 4*b
    const float alpha = 4.0f * (g_absmax[0] / 127.0f) * (g_absmax[1] / 127.0f);

    #pragma unroll
    for (int mi = 0; mi < 4; ++mi) {
        const int r0 = bm0 + wm * 64 + mi * 16 + (lane >> 2);
        #pragma unroll
        for (int ni = 0; ni < 4; ++ni) {
            const int c0 = bn0 + wn * 32 + ni * 8 + (lane & 3) * 2;
            const float b0v = 4.0f * bias[c0];
            const float b1v = 4.0f * bias[c0 + 1];
            float* o0 = C + (size_t)r0 * N_DIM + c0;
            o0[0] = alpha * acc[mi][ni][0] + b0v;
            o0[1] = alpha * acc[mi][ni][1] + b1v;
            float* o1 = C + (size_t)(r0 + 8) * N_DIM + c0;
            o1[0] = alpha * acc[mi][ni][2] + b0v;
            o1[1] = alpha * acc[mi][ni][3] + b1v;
        }
    }
}

// ---------------- launch ----------------
extern "C" void kernel_launch(void* const* d_in, const int* in_sizes, int n_in,
                              void* d_out, int out_size) {
    const float* x = (const float*)d_in[0];
    const float* W = (const float*)d_in[1];
    const float* b = (const float*)d_in[2];
    float* out = (float*)d_out;

    const int n4x = (M_DIM * K_DIM) / 4;
    const int n4w = (N_DIM * K_DIM) / 4;
    const int n8x = (M_DIM * K_DIM) / 8;
    const int n8w = (N_DIM * K_DIM) / 8;

    init_kernel<<<1, 32>>>();
    absmax_kernel<<<2048, 256>>>((const float4*)x, n4x, 0);
    absmax_kernel<<<2048, 256>>>((const float4*)W, n4w, 1);
    quant_x_kernel<<<(n8x + 255) / 256, 256>>>((const float4*)x, n8x);
    quant_w_kernel<<<(n8w + 255) / 256, 256>>>((const float4*)W, n8w);

    static bool attr_set = false;
    if (!attr_set) {
        cudaFuncSetAttribute(gemm_kernel,
                             cudaFuncAttributeMaxDynamicSharedMemorySize, SMEM_DYN);
        attr_set = true;
    }
    dim3 grid(N_DIM / BN, M_DIM / BM);  // (16, 64)
    gemm_kernel<<<grid, NTHREADS, SMEM_DYN>>>(out, b);
}

// round 12
// speedup vs baseline: 1.0575x; 1.0575x over previous
#include <cuda_runtime.h>
#include <cuda_bf16.h>
#include <cstdint>

#define M_DIM 8192
#define N_DIM 4096
#define K_DIM 4096

// ---------------- scratch (no allocations allowed) ----------------
__device__ float g_absmax[2];                         // [0]=x, [1]=W
__device__ __nv_bfloat16 g_qx[(size_t)M_DIM * K_DIM]; // 64 MB
__device__ __nv_bfloat16 g_qw[(size_t)N_DIM * K_DIM]; // 32 MB

// ---------------- init ----------------
__global__ void init_kernel() {
    if (threadIdx.x < 2) g_absmax[threadIdx.x] = 0.0f;
}

// ---------------- absmax reduction (2-way ILP, big grid) ----------------
__global__ void absmax_kernel(const float4* __restrict__ p, int n4, int slot) {
    float m = 0.0f;
    const int stride = gridDim.x * blockDim.x;
    int i = blockIdx.x * blockDim.x + threadIdx.x;
    for (; i + stride < n4; i += 2 * stride) {
        float4 v0 = p[i];
        float4 v1 = p[i + stride];
        float a = fmaxf(fmaxf(fabsf(v0.x), fabsf(v0.y)),
                        fmaxf(fabsf(v0.z), fabsf(v0.w)));
        float b = fmaxf(fmaxf(fabsf(v1.x), fabsf(v1.y)),
                        fmaxf(fabsf(v1.z), fabsf(v1.w)));
        m = fmaxf(m, fmaxf(a, b));
    }
    if (i < n4) {
        float4 v = p[i];
        m = fmaxf(m, fmaxf(fmaxf(fabsf(v.x), fabsf(v.y)),
                           fmaxf(fabsf(v.z), fabsf(v.w))));
    }
    #pragma unroll
    for (int o = 16; o; o >>= 1) m = fmaxf(m, __shfl_xor_sync(0xFFFFFFFFu, m, o));
    __shared__ float sm[32];
    if ((threadIdx.x & 31) == 0) sm[threadIdx.x >> 5] = m;
    __syncthreads();
    if (threadIdx.x < 32) {
        m = (threadIdx.x < (blockDim.x >> 5)) ? sm[threadIdx.x] : 0.0f;
        #pragma unroll
        for (int o = 16; o; o >>= 1) m = fmaxf(m, __shfl_xor_sync(0xFFFFFFFFu, m, o));
        if (threadIdx.x == 0)
            atomicMax((unsigned int*)&g_absmax[slot], __float_as_uint(m));
    }
}

// ---------------- quantize to integer-valued bf16 (8 elems/thread) ----------------
__device__ __forceinline__ uint32_t qpack2(float a, float b, float s, float lo) {
    float q0 = fminf(fmaxf(rintf(a / s), lo), 127.0f);
    float q1 = fminf(fmaxf(rintf(b / s), lo), 127.0f);
    __nv_bfloat162 h = __floats2bfloat162_rn(q0, q1);
    return *(uint32_t*)&h;
}

__global__ void quant_x_kernel(const float4* __restrict__ in, int n8) {
    int i = blockIdx.x * blockDim.x + threadIdx.x;
    if (i >= n8) return;
    const float s = g_absmax[0] / 127.0f;
    float4 v0 = in[i * 2 + 0];
    float4 v1 = in[i * 2 + 1];
    uint4 o;
    o.x = qpack2(v0.x, v0.y, s, -128.0f);
    o.y = qpack2(v0.z, v0.w, s, -128.0f);
    o.z = qpack2(v1.x, v1.y, s, -128.0f);
    o.w = qpack2(v1.z, v1.w, s, -128.0f);
    ((uint4*)g_qx)[i] = o;   // device-side symbol binding (round-7 lesson)
}

__global__ void quant_w_kernel(const float4* __restrict__ in, int n8) {
    int i = blockIdx.x * blockDim.x + threadIdx.x;
    if (i >= n8) return;
    const float s = g_absmax[1] / 127.0f;
    float4 v0 = in[i * 2 + 0];
    float4 v1 = in[i * 2 + 1];
    uint4 o;
    o.x = qpack2(v0.x, v0.y, s, -127.0f);
    o.y = qpack2(v0.z, v0.w, s, -127.0f);
    o.z = qpack2(v1.x, v1.y, s, -127.0f);
    o.w = qpack2(v1.z, v1.w, s, -127.0f);
    ((uint4*)g_qw)[i] = o;
}

// ---------------- GEMM: C[M,N] = qx[M,K] * qw[N,K]^T ----------------
// 128x128 CTA tile, 256 threads (8 warps, 64x32 warp tiles), 3-stage ring,
// 96 KB smem -> 2 CTAs/SM. Two independent CTAs per SM cover each other's
// barrier/wait bubbles (round-11 lesson: in-warp pipelining can't).
#define BM 128
#define BN 128
#define BK 64          // 64 bf16 = 128 bytes per row
#define NTHREADS 256
#define NSTAGE 3
#define KT (K_DIM / BK)            // 64
#define A_BYTES (BM * 128)         // 16 KB
#define B_BYTES (BN * 128)         // 16 KB
#define STAGE_BYTES (A_BYTES + B_BYTES)        // 32 KB
#define SMEM_DYN (NSTAGE * STAGE_BYTES + 128)  // 96 KB + pad

__device__ __forceinline__ unsigned smem_u32(const void* p) {
    return (unsigned)__cvta_generic_to_shared(p);
}

__device__ __forceinline__ void ldsm4(unsigned r[4], unsigned addr) {
    asm volatile("ldmatrix.sync.aligned.m8n8.x4.shared.b16 {%0,%1,%2,%3}, [%4];"
                 : "=r"(r[0]), "=r"(r[1]), "=r"(r[2]), "=r"(r[3])
                 : "r"(addr));
}

__device__ __forceinline__ void mma_bf16(float c[4],
                                         unsigned a0, unsigned a1, unsigned a2, unsigned a3,
                                         unsigned b0, unsigned b1) {
    asm volatile(
        "mma.sync.aligned.m16n8k16.row.col.f32.bf16.bf16.f32 "
        "{%0,%1,%2,%3}, {%4,%5,%6,%7}, {%8,%9}, {%0,%1,%2,%3};"
        : "+f"(c[0]), "+f"(c[1]), "+f"(c[2]), "+f"(c[3])
        : "r"(a0), "r"(a1), "r"(a2), "r"(a3), "r"(b0), "r"(b1));
}

__global__ __launch_bounds__(NTHREADS, 2) void gemm_kernel(float* __restrict__ C,
                                                           const float* __restrict__ bias) {
    extern __shared__ __align__(128) uint8_t dynsmem[];
    uint32_t smbase = smem_u32(dynsmem);
    smbase = (smbase + 127u) & ~127u;

    const int tid  = threadIdx.x;
    const int lane = tid & 31;
    const int warp = tid >> 5;
    const int wm   = warp >> 2;   // 0..1  (64 rows)
    const int wn   = warp & 3;    // 0..3  (32 cols)
    const int bm0  = blockIdx.y * BM;
    const int bn0  = blockIdx.x * BN;

    const __nv_bfloat16* gA = g_qx + (size_t)bm0 * K_DIM;
    const __nv_bfloat16* gB = g_qw + (size_t)bn0 * K_DIM;

    float acc[4][4][4];
    #pragma unroll
    for (int mi = 0; mi < 4; ++mi)
        #pragma unroll
        for (int ni = 0; ni < 4; ++ni)
            #pragma unroll
            for (int r = 0; r < 4; ++r) acc[mi][ni][r] = 0.0f;

    // stage loader: A = 1024 chunks (4/thread), B = 1024 chunks (4/thread)
    auto load_stage = [&](int kt, int stage) {
        const uint32_t sa = smbase + stage * STAGE_BYTES;
        const uint32_t sb = sa + A_BYTES;
        const int k0 = kt * BK;
        #pragma unroll
        for (int i = 0; i < 4; ++i) {
            const int id  = tid + i * NTHREADS;
            const int row = id >> 3, ch = id & 7;
            const uint32_t off = row * 128 + ((ch ^ (row & 7)) << 4);
            const void* srcA = gA + (size_t)row * K_DIM + k0 + ch * 8;
            asm volatile("cp.async.cg.shared.global [%0], [%1], 16;\n"
                         :: "r"(sa + off), "l"(srcA));
            const void* srcB = gB + (size_t)row * K_DIM + k0 + ch * 8;
            asm volatile("cp.async.cg.shared.global [%0], [%1], 16;\n"
                         :: "r"(sb + off), "l"(srcB));
        }
        asm volatile("cp.async.commit_group;\n" ::: "memory");
    };

    load_stage(0, 0);
    load_stage(1, 1);

    // fragment address components
    const int arow[4] = {wm * 64 + 0 * 16 + (lane & 15), wm * 64 + 1 * 16 + (lane & 15),
                         wm * 64 + 2 * 16 + (lane & 15), wm * 64 + 3 * 16 + (lane & 15)};
    const int abit = lane >> 4;
    const int brow[2] = {wn * 32 + 0 * 16 + (lane & 7) + ((lane >> 4) << 3),
                         wn * 32 + 1 * 16 + (lane & 7) + ((lane >> 4) << 3)};
    const int bbit = (lane >> 3) & 1;

    int stage = 0;
    for (int kt = 0; kt < KT; ++kt) {
        asm volatile("cp.async.wait_group 1;\n" ::: "memory");
        __syncthreads();
        // refill the stage freed at kt-1 (all warps passed the barrier => done reading)
        if (kt + 2 < KT) {
            int st = stage + 2; if (st >= NSTAGE) st -= NSTAGE;
            load_stage(kt + 2, st);
        } else {
            asm volatile("cp.async.commit_group;\n" ::: "memory");
        }

        const uint32_t sa = smbase + stage * STAGE_BYTES;
        const uint32_t sb = sa + A_BYTES;

        #pragma unroll
        for (int ks = 0; ks < 4; ++ks) {        // BK/16
            unsigned af[4][4], bf[2][4];
            #pragma unroll
            for (int mi = 0; mi < 4; ++mi) {
                const int ch = ks * 2 + abit;
                ldsm4(af[mi], sa + arow[mi] * 128 + ((ch ^ (arow[mi] & 7)) << 4));
            }
            #pragma unroll
            for (int nj = 0; nj < 2; ++nj) {
                const int ch = ks * 2 + bbit;
                ldsm4(bf[nj], sb + brow[nj] * 128 + ((ch ^ (brow[nj] & 7)) << 4));
            }
            #pragma unroll
            for (int mi = 0; mi < 4; ++mi)
                #pragma unroll
                for (int ni = 0; ni < 4; ++ni)
                    mma_bf16(acc[mi][ni],
                             af[mi][0], af[mi][1], af[mi][2], af[mi][3],
                             bf[ni >> 1][(ni & 1) * 2], bf[ni >> 1][(ni & 1) * 2 + 1]);
        }
        if (++stage == NSTAGE) stage = 0;
    }

    // epilogue: out = (4*s_x*s_w)*acc + 4*b
    const float alpha = 4.0f * (g_absmax[0] / 127.0f) * (g_absmax[1] / 127.0f);

    #pragma unroll
    for (int mi = 0; mi < 4; ++mi) {
        const int r0 = bm0 + wm * 64 + mi * 16 + (lane >> 2);
        #pragma unroll
        for (int ni = 0; ni < 4; ++ni) {
            const int c0 = bn0 + wn * 32 + ni * 8 + (lane & 3) * 2;
            const float b0v = 4.0f * bias[c0];
            const float b1v = 4.0f * bias[c0 + 1];
            float* o0 = C + (size_t)r0 * N_DIM + c0;
            o0[0] = alpha * acc[mi][ni][0] + b0v;
            o0[1] = alpha * acc[mi][ni][1] + b1v;
            float* o1 = C + (size_t)(r0 + 8) * N_DIM + c0;
            o1[0] = alpha * acc[mi][ni][2] + b0v;
            o1[1] = alpha * acc[mi][ni][3] + b1v;
        }
    }
}

// ---------------- launch ----------------
extern "C" void kernel_launch(void* const* d_in, const int* in_sizes, int n_in,
                              void* d_out, int out_size) {
    const float* x = (const float*)d_in[0];
    const float* W = (const float*)d_in[1];
    const float* b = (const float*)d_in[2];
    float* out = (float*)d_out;

    const int n4x = (M_DIM * K_DIM) / 4;
    const int n4w = (N_DIM * K_DIM) / 4;
    const int n8x = (M_DIM * K_DIM) / 8;
    const int n8w = (N_DIM * K_DIM) / 8;

    init_kernel<<<1, 32>>>();
    absmax_kernel<<<8192, 256>>>((const float4*)x, n4x, 0);
    absmax_kernel<<<4096, 256>>>((const float4*)W, n4w, 1);
    quant_x_kernel<<<(n8x + 255) / 256, 256>>>((const float4*)x, n8x);
    quant_w_kernel<<<(n8w + 255) / 256, 256>>>((const float4*)W, n8w);

    static bool attr_set = false;
    if (!attr_set) {
        cudaFuncSetAttribute(gemm_kernel,
                             cudaFuncAttributeMaxDynamicSharedMemorySize, SMEM_DYN);
        attr_set = true;
    }
    dim3 grid(N_DIM / BN, M_DIM / BM);  // (32, 64): x-fast over N for L2 reuse
    gemm_kernel<<<grid, NTHREADS, SMEM_DYN>>>(out, b);
}

// round 13
// speedup vs baseline: 1.0885x; 1.0293x over previous
#include <cuda_runtime.h>
#include <cuda_bf16.h>
#include <cstdint>

#define M_DIM 8192
#define N_DIM 4096
#define K_DIM 4096

// ---------------- scratch (no allocations allowed) ----------------
__device__ float g_absmax[2];                         // [0]=x, [1]=W
__device__ __nv_bfloat16 g_qx[(size_t)M_DIM * K_DIM]; // 64 MB
__device__ __nv_bfloat16 g_qw[(size_t)N_DIM * K_DIM]; // 32 MB

// ---------------- init ----------------
__global__ void init_kernel() {
    if (threadIdx.x < 2) g_absmax[threadIdx.x] = 0.0f;
}

// ---------------- fused absmax: blocks [0,bx) -> x, rest -> w ----------------
#define AMAX_BX 6144
#define AMAX_BW 3072
__global__ void absmax_fused_kernel(const float4* __restrict__ px, int n4x,
                                    const float4* __restrict__ pw, int n4w) {
    const int isw  = (blockIdx.x >= AMAX_BX);
    const float4* __restrict__ p = isw ? pw : px;
    const int n4      = isw ? n4w : n4x;
    const int blk     = isw ? (blockIdx.x - AMAX_BX) : blockIdx.x;
    const int nblk    = isw ? AMAX_BW : AMAX_BX;
    const int stride  = nblk * blockDim.x;

    float m = 0.0f;
    int i = blk * blockDim.x + threadIdx.x;
    for (; i + 3 * stride < n4; i += 4 * stride) {
        float4 v0 = p[i];
        float4 v1 = p[i + stride];
        float4 v2 = p[i + 2 * stride];
        float4 v3 = p[i + 3 * stride];
        float a = fmaxf(fmaxf(fabsf(v0.x), fabsf(v0.y)), fmaxf(fabsf(v0.z), fabsf(v0.w)));
        float b = fmaxf(fmaxf(fabsf(v1.x), fabsf(v1.y)), fmaxf(fabsf(v1.z), fabsf(v1.w)));
        float c = fmaxf(fmaxf(fabsf(v2.x), fabsf(v2.y)), fmaxf(fabsf(v2.z), fabsf(v2.w)));
        float d = fmaxf(fmaxf(fabsf(v3.x), fabsf(v3.y)), fmaxf(fabsf(v3.z), fabsf(v3.w)));
        m = fmaxf(m, fmaxf(fmaxf(a, b), fmaxf(c, d)));
    }
    for (; i < n4; i += stride) {
        float4 v = p[i];
        m = fmaxf(m, fmaxf(fmaxf(fabsf(v.x), fabsf(v.y)), fmaxf(fabsf(v.z), fabsf(v.w))));
    }
    #pragma unroll
    for (int o = 16; o; o >>= 1) m = fmaxf(m, __shfl_xor_sync(0xFFFFFFFFu, m, o));
    __shared__ float sm[32];
    if ((threadIdx.x & 31) == 0) sm[threadIdx.x >> 5] = m;
    __syncthreads();
    if (threadIdx.x < 32) {
        m = (threadIdx.x < (blockDim.x >> 5)) ? sm[threadIdx.x] : 0.0f;
        #pragma unroll
        for (int o = 16; o; o >>= 1) m = fmaxf(m, __shfl_xor_sync(0xFFFFFFFFu, m, o));
        if (threadIdx.x == 0)
            atomicMax((unsigned int*)&g_absmax[isw], __float_as_uint(m));
    }
}

// ---------------- fused quantize: blocks [0,bx) -> x, rest -> w ----------------
__device__ __forceinline__ uint32_t qpack2(float a, float b, float s, float lo) {
    float q0 = fminf(fmaxf(rintf(a / s), lo), 127.0f);
    float q1 = fminf(fmaxf(rintf(b / s), lo), 127.0f);
    __nv_bfloat162 h = __floats2bfloat162_rn(q0, q1);
    return *(uint32_t*)&h;
}

__global__ void quant_fused_kernel(const float4* __restrict__ xin, int n8x, int bx,
                                   const float4* __restrict__ win, int n8w) {
    const int isw = (blockIdx.x >= bx);
    const float4* __restrict__ in = isw ? win : xin;
    const int n8  = isw ? n8w : n8x;
    const float lo = isw ? -127.0f : -128.0f;
    const int i = (isw ? (blockIdx.x - bx) : blockIdx.x) * blockDim.x + threadIdx.x;
    if (i >= n8) return;
    const float s = g_absmax[isw] / 127.0f;
    float4 v0 = in[i * 2 + 0];
    float4 v1 = in[i * 2 + 1];
    uint4 o;
    o.x = qpack2(v0.x, v0.y, s, lo);
    o.y = qpack2(v0.z, v0.w, s, lo);
    o.z = qpack2(v1.x, v1.y, s, lo);
    o.w = qpack2(v1.z, v1.w, s, lo);
    // device-side symbol binding (round-7 lesson)
    if (isw) ((uint4*)g_qw)[i] = o;
    else     ((uint4*)g_qx)[i] = o;
}

// ---------------- GEMM: C[M,N] = qx[M,K] * qw[N,K]^T ----------------
// 128x128 CTA tile, 256 threads (8 warps, 64x32 warp tiles), 3-stage ring,
// 96 KB smem -> 2 CTAs/SM (independent CTAs cover each other's barrier bubbles).
#define BM 128
#define BN 128
#define BK 64          // 64 bf16 = 128 bytes per row
#define NTHREADS 256
#define NSTAGE 3
#define KT (K_DIM / BK)            // 64
#define A_BYTES (BM * 128)         // 16 KB
#define B_BYTES (BN * 128)         // 16 KB
#define STAGE_BYTES (A_BYTES + B_BYTES)        // 32 KB
#define SMEM_DYN (NSTAGE * STAGE_BYTES + 128)  // 96 KB + pad

__device__ __forceinline__ unsigned smem_u32(const void* p) {
    return (unsigned)__cvta_generic_to_shared(p);
}

__device__ __forceinline__ void ldsm4(unsigned r[4], unsigned addr) {
    asm volatile("ldmatrix.sync.aligned.m8n8.x4.shared.b16 {%0,%1,%2,%3}, [%4];"
                 : "=r"(r[0]), "=r"(r[1]), "=r"(r[2]), "=r"(r[3])
                 : "r"(addr));
}

__device__ __forceinline__ void mma_bf16(float c[4],
                                         unsigned a0, unsigned a1, unsigned a2, unsigned a3,
                                         unsigned b0, unsigned b1) {
    asm volatile(
        "mma.sync.aligned.m16n8k16.row.col.f32.bf16.bf16.f32 "
        "{%0,%1,%2,%3}, {%4,%5,%6,%7}, {%8,%9}, {%0,%1,%2,%3};"
        : "+f"(c[0]), "+f"(c[1]), "+f"(c[2]), "+f"(c[3])
        : "r"(a0), "r"(a1), "r"(a2), "r"(a3), "r"(b0), "r"(b1));
}

__global__ __launch_bounds__(NTHREADS, 2) void gemm_kernel(float* __restrict__ C,
                                                           const float* __restrict__ bias) {
    extern __shared__ __align__(128) uint8_t dynsmem[];
    uint32_t smbase = smem_u32(dynsmem);
    smbase = (smbase + 127u) & ~127u;

    const int tid  = threadIdx.x;
    const int lane = tid & 31;
    const int warp = tid >> 5;
    const int wm   = warp >> 2;   // 0..1  (64 rows)
    const int wn   = warp & 3;    // 0..3  (32 cols)
    const int bm0  = blockIdx.y * BM;
    const int bn0  = blockIdx.x * BN;

    const __nv_bfloat16* gA = g_qx + (size_t)bm0 * K_DIM;
    const __nv_bfloat16* gB = g_qw + (size_t)bn0 * K_DIM;

    float acc[4][4][4];
    #pragma unroll
    for (int mi = 0; mi < 4; ++mi)
        #pragma unroll
        for (int ni = 0; ni < 4; ++ni)
            #pragma unroll
            for (int r = 0; r < 4; ++r) acc[mi][ni][r] = 0.0f;

    // stage loader: A = 1024 chunks (4/thread), B = 1024 chunks (4/thread)
    auto load_stage = [&](int kt, int stage) {
        const uint32_t sa = smbase + stage * STAGE_BYTES;
        const uint32_t sb = sa + A_BYTES;
        const int k0 = kt * BK;
        #pragma unroll
        for (int i = 0; i < 4; ++i) {
            const int id  = tid + i * NTHREADS;
            const int row = id >> 3, ch = id & 7;
            const uint32_t off = row * 128 + ((ch ^ (row & 7)) << 4);
            const void* srcA = gA + (size_t)row * K_DIM + k0 + ch * 8;
            asm volatile("cp.async.cg.shared.global [%0], [%1], 16;\n"
                         :: "r"(sa + off), "l"(srcA));
            const void* srcB = gB + (size_t)row * K_DIM + k0 + ch * 8;
            asm volatile("cp.async.cg.shared.global [%0], [%1], 16;\n"
                         :: "r"(sb + off), "l"(srcB));
        }
        asm volatile("cp.async.commit_group;\n" ::: "memory");
    };

    load_stage(0, 0);
    load_stage(1, 1);

    // fragment address components
    const int arow[4] = {wm * 64 + 0 * 16 + (lane & 15), wm * 64 + 1 * 16 + (lane & 15),
                         wm * 64 + 2 * 16 + (lane & 15), wm * 64 + 3 * 16 + (lane & 15)};
    const int abit = lane >> 4;
    const int brow[2] = {wn * 32 + 0 * 16 + (lane & 7) + ((lane >> 4) << 3),
                         wn * 32 + 1 * 16 + (lane & 7) + ((lane >> 4) << 3)};
    const int bbit = (lane >> 3) & 1;

    int stage = 0;
    for (int kt = 0; kt < KT; ++kt) {
        asm volatile("cp.async.wait_group 1;\n" ::: "memory");
        __syncthreads();
        // refill the stage freed at kt-1 (all warps passed the barrier => done reading)
        if (kt + 2 < KT) {
            int st = stage + 2; if (st >= NSTAGE) st -= NSTAGE;
            load_stage(kt + 2, st);
        } else {
            asm volatile("cp.async.commit_group;\n" ::: "memory");
        }

        const uint32_t sa = smbase + stage * STAGE_BYTES;
        const uint32_t sb = sa + A_BYTES;

        #pragma unroll
        for (int ks = 0; ks < 4; ++ks) {        // BK/16
            unsigned af[4][4], bf[2][4];
            #pragma unroll
            for (int mi = 0; mi < 4; ++mi) {
                const int ch = ks * 2 + abit;
                ldsm4(af[mi], sa + arow[mi] * 128 + ((ch ^ (arow[mi] & 7)) << 4));
            }
            #pragma unroll
            for (int nj = 0; nj < 2; ++nj) {
                const int ch = ks * 2 + bbit;
                ldsm4(bf[nj], sb + brow[nj] * 128 + ((ch ^ (brow[nj] & 7)) << 4));
            }
            #pragma unroll
            for (int mi = 0; mi < 4; ++mi)
                #pragma unroll
                for (int ni = 0; ni < 4; ++ni)
                    mma_bf16(acc[mi][ni],
                             af[mi][0], af[mi][1], af[mi][2], af[mi][3],
                             bf[ni >> 1][(ni & 1) * 2], bf[ni >> 1][(ni & 1) * 2 + 1]);
        }
        if (++stage == NSTAGE) stage = 0;
    }

    // epilogue: out = (4*s_x*s_w)*acc + 4*b
    // stores use .cs (evict-first) so the 128 MB output stream does not evict
    // the 96 MB qx/qw L2 working set that later waves re-read.
    const float alpha = 4.0f * (g_absmax[0] / 127.0f) * (g_absmax[1] / 127.0f);

    #pragma unroll
    for (int mi = 0; mi < 4; ++mi) {
        const int r0 = bm0 + wm * 64 + mi * 16 + (lane >> 2);
        #pragma unroll
        for (int ni = 0; ni < 4; ++ni) {
            const int c0 = bn0 + wn * 32 + ni * 8 + (lane & 3) * 2;
            const float b0v = 4.0f * bias[c0];
            const float b1v = 4.0f * bias[c0 + 1];
            float2 o0 = make_float2(alpha * acc[mi][ni][0] + b0v,
                                    alpha * acc[mi][ni][1] + b1v);
            float2 o1 = make_float2(alpha * acc[mi][ni][2] + b0v,
                                    alpha * acc[mi][ni][3] + b1v);
            __stcs((float2*)(C + (size_t)r0 * N_DIM + c0), o0);
            __stcs((float2*)(C + (size_t)(r0 + 8) * N_DIM + c0), o1);
        }
    }
}

// ---------------- launch ----------------
extern "C" void kernel_launch(void* const* d_in, const int* in_sizes, int n_in,
                              void* d_out, int out_size) {
    const float* x = (const float*)d_in[0];
    const float* W = (const float*)d_in[1];
    const float* b = (const float*)d_in[2];
    float* out = (float*)d_out;

    const int n4x = (M_DIM * K_DIM) / 4;
    const int n4w = (N_DIM * K_DIM) / 4;
    const int n8x = (M_DIM * K_DIM) / 8;
    const int n8w = (N_DIM * K_DIM) / 8;

    init_kernel<<<1, 32>>>();
    absmax_fused_kernel<<<AMAX_BX + AMAX_BW, 256>>>((const float4*)x, n4x,
                                                    (const float4*)W, n4w);
    const int qbx = (n8x + 255) / 256;
    const int qbw = (n8w + 255) / 256;
    quant_fused_kernel<<<qbx + qbw, 256>>>((const float4*)x, n8x, qbx,
                                           (const float4*)W, n8w);

    static bool attr_set = false;
    if (!attr_set) {
        cudaFuncSetAttribute(gemm_kernel,
                             cudaFuncAttributeMaxDynamicSharedMemorySize, SMEM_DYN);
        attr_set = true;
    }
    dim3 grid(N_DIM / BN, M_DIM / BM);  // (32, 64): x-fast over N for L2 reuse
    gemm_kernel<<<grid, NTHREADS, SMEM_DYN>>>(out, b);
}

// round 14
// speedup vs baseline: 1.1183x; 1.0275x over previous
#include <cuda_runtime.h>
#include <cuda_bf16.h>
#include <cstdint>

#define M_DIM 8192
#define N_DIM 4096
#define K_DIM 4096

// ---------------- scratch (no allocations allowed) ----------------
__device__ float g_absmax[2];                         // [0]=x, [1]=W
__device__ __nv_bfloat16 g_qx[(size_t)M_DIM * K_DIM]; // 64 MB
__device__ __nv_bfloat16 g_qw[(size_t)N_DIM * K_DIM]; // 32 MB

// ---------------- init ----------------
__global__ void init_kernel() {
    if (threadIdx.x < 2) g_absmax[threadIdx.x] = 0.0f;
}

// ---------------- fused absmax: blocks [0,bx) -> x, rest -> w ----------------
#define AMAX_BX 6144
#define AMAX_BW 3072
__global__ void absmax_fused_kernel(const float4* __restrict__ px, int n4x,
                                    const float4* __restrict__ pw, int n4w) {
    const int isw  = (blockIdx.x >= AMAX_BX);
    const float4* __restrict__ p = isw ? pw : px;
    const int n4      = isw ? n4w : n4x;
    const int blk     = isw ? (blockIdx.x - AMAX_BX) : blockIdx.x;
    const int nblk    = isw ? AMAX_BW : AMAX_BX;
    const int stride  = nblk * blockDim.x;

    float m = 0.0f;
    int i = blk * blockDim.x + threadIdx.x;
    for (; i + 3 * stride < n4; i += 4 * stride) {
        float4 v0 = p[i];
        float4 v1 = p[i + stride];
        float4 v2 = p[i + 2 * stride];
        float4 v3 = p[i + 3 * stride];
        float a = fmaxf(fmaxf(fabsf(v0.x), fabsf(v0.y)), fmaxf(fabsf(v0.z), fabsf(v0.w)));
        float b = fmaxf(fmaxf(fabsf(v1.x), fabsf(v1.y)), fmaxf(fabsf(v1.z), fabsf(v1.w)));
        float c = fmaxf(fmaxf(fabsf(v2.x), fabsf(v2.y)), fmaxf(fabsf(v2.z), fabsf(v2.w)));
        float d = fmaxf(fmaxf(fabsf(v3.x), fabsf(v3.y)), fmaxf(fabsf(v3.z), fabsf(v3.w)));
        m = fmaxf(m, fmaxf(fmaxf(a, b), fmaxf(c, d)));
    }
    for (; i < n4; i += stride) {
        float4 v = p[i];
        m = fmaxf(m, fmaxf(fmaxf(fabsf(v.x), fabsf(v.y)), fmaxf(fabsf(v.z), fabsf(v.w))));
    }
    #pragma unroll
    for (int o = 16; o; o >>= 1) m = fmaxf(m, __shfl_xor_sync(0xFFFFFFFFu, m, o));
    __shared__ float sm[32];
    if ((threadIdx.x & 31) == 0) sm[threadIdx.x >> 5] = m;
    __syncthreads();
    if (threadIdx.x < 32) {
        m = (threadIdx.x < (blockDim.x >> 5)) ? sm[threadIdx.x] : 0.0f;
        #pragma unroll
        for (int o = 16; o; o >>= 1) m = fmaxf(m, __shfl_xor_sync(0xFFFFFFFFu, m, o));
        if (threadIdx.x == 0)
            atomicMax((unsigned int*)&g_absmax[isw], __float_as_uint(m));
    }
}

// ---------------- fused quantize: blocks [0,bx) -> x, rest -> w ----------------
__device__ __forceinline__ uint32_t qpack2(float a, float b, float si, float lo) {
    float q0 = fminf(fmaxf(rintf(a * si), lo), 127.0f);
    float q1 = fminf(fmaxf(rintf(b * si), lo), 127.0f);
    __nv_bfloat162 h = __floats2bfloat162_rn(q0, q1);
    return *(uint32_t*)&h;
}

__global__ void quant_fused_kernel(const float4* __restrict__ xin, int n8x, int bx,
                                   const float4* __restrict__ win, int n8w) {
    const int isw = (blockIdx.x >= bx);
    const float4* __restrict__ in = isw ? win : xin;
    const int n8  = isw ? n8w : n8x;
    const float lo = isw ? -127.0f : -128.0f;
    const int i = (isw ? (blockIdx.x - bx) : blockIdx.x) * blockDim.x + threadIdx.x;
    if (i >= n8) return;
    const float si = 127.0f / g_absmax[isw];   // reciprocal once; no per-elem FDIV
    float4 v0 = in[i * 2 + 0];
    float4 v1 = in[i * 2 + 1];
    uint4 o;
    o.x = qpack2(v0.x, v0.y, si, lo);
    o.y = qpack2(v0.z, v0.w, si, lo);
    o.z = qpack2(v1.x, v1.y, si, lo);
    o.w = qpack2(v1.z, v1.w, si, lo);
    // device-side symbol binding (round-7 lesson)
    if (isw) ((uint4*)g_qw)[i] = o;
    else     ((uint4*)g_qx)[i] = o;
}

// ---------------- GEMM: C[M,N] = qx[M,K] * qw[N,K]^T ----------------
// 128x128 CTA tile, 128 threads: 4 warps of 64x64 tiles (2x2). Halves smem
// fragment traffic per MMA vs 8x(64x32) (round-13 ncu: smem port ~82% busy).
// 3-stage ring, 96 KB smem -> 2 CTAs/SM for barrier-bubble covering.
#define BM 128
#define BN 128
#define BK 64          // 64 bf16 = 128 bytes per row
#define NTHREADS 128
#define NSTAGE 3
#define KT (K_DIM / BK)            // 64
#define A_BYTES (BM * 128)         // 16 KB
#define B_BYTES (BN * 128)         // 16 KB
#define STAGE_BYTES (A_BYTES + B_BYTES)        // 32 KB
#define SMEM_DYN (NSTAGE * STAGE_BYTES + 128)  // 96 KB + pad

__device__ __forceinline__ unsigned smem_u32(const void* p) {
    return (unsigned)__cvta_generic_to_shared(p);
}

__device__ __forceinline__ void ldsm4(unsigned r[4], unsigned addr) {
    asm volatile("ldmatrix.sync.aligned.m8n8.x4.shared.b16 {%0,%1,%2,%3}, [%4];"
                 : "=r"(r[0]), "=r"(r[1]), "=r"(r[2]), "=r"(r[3])
                 : "r"(addr));
}

__device__ __forceinline__ void mma_bf16(float c[4],
                                         unsigned a0, unsigned a1, unsigned a2, unsigned a3,
                                         unsigned b0, unsigned b1) {
    asm volatile(
        "mma.sync.aligned.m16n8k16.row.col.f32.bf16.bf16.f32 "
        "{%0,%1,%2,%3}, {%4,%5,%6,%7}, {%8,%9}, {%0,%1,%2,%3};"
        : "+f"(c[0]), "+f"(c[1]), "+f"(c[2]), "+f"(c[3])
        : "r"(a0), "r"(a1), "r"(a2), "r"(a3), "r"(b0), "r"(b1));
}

__global__ __launch_bounds__(NTHREADS, 2) void gemm_kernel(float* __restrict__ C,
                                                           const float* __restrict__ bias) {
    extern __shared__ __align__(128) uint8_t dynsmem[];
    uint32_t smbase = smem_u32(dynsmem);
    smbase = (smbase + 127u) & ~127u;

    const int tid  = threadIdx.x;
    const int lane = tid & 31;
    const int warp = tid >> 5;
    const int wm   = warp >> 1;   // 0..1  (64 rows)
    const int wn   = warp & 1;    // 0..1  (64 cols)
    const int bm0  = blockIdx.y * BM;
    const int bn0  = blockIdx.x * BN;

    const __nv_bfloat16* gA = g_qx + (size_t)bm0 * K_DIM;
    const __nv_bfloat16* gB = g_qw + (size_t)bn0 * K_DIM;

    float acc[4][8][4];
    #pragma unroll
    for (int mi = 0; mi < 4; ++mi)
        #pragma unroll
        for (int ni = 0; ni < 8; ++ni)
            #pragma unroll
            for (int r = 0; r < 4; ++r) acc[mi][ni][r] = 0.0f;

    // stage loader: A = 1024 chunks (8/thread), B = 1024 chunks (8/thread)
    auto load_stage = [&](int kt, int stage) {
        const uint32_t sa = smbase + stage * STAGE_BYTES;
        const uint32_t sb = sa + A_BYTES;
        const int k0 = kt * BK;
        #pragma unroll
        for (int i = 0; i < 8; ++i) {
            const int id  = tid + i * NTHREADS;
            const int row = id >> 3, ch = id & 7;
            const uint32_t off = row * 128 + ((ch ^ (row & 7)) << 4);
            const void* srcA = gA + (size_t)row * K_DIM + k0 + ch * 8;
            asm volatile("cp.async.cg.shared.global [%0], [%1], 16;\n"
                         :: "r"(sa + off), "l"(srcA));
            const void* srcB = gB + (size_t)row * K_DIM + k0 + ch * 8;
            asm volatile("cp.async.cg.shared.global [%0], [%1], 16;\n"
                         :: "r"(sb + off), "l"(srcB));
        }
        asm volatile("cp.async.commit_group;\n" ::: "memory");
    };

    load_stage(0, 0);
    load_stage(1, 1);

    // fragment address components
    const int arow[4] = {wm * 64 + 0 * 16 + (lane & 15), wm * 64 + 1 * 16 + (lane & 15),
                         wm * 64 + 2 * 16 + (lane & 15), wm * 64 + 3 * 16 + (lane & 15)};
    const int abit = lane >> 4;
    const int brow[4] = {wn * 64 + 0 * 16 + (lane & 7) + ((lane >> 4) << 3),
                         wn * 64 + 1 * 16 + (lane & 7) + ((lane >> 4) << 3),
                         wn * 64 + 2 * 16 + (lane & 7) + ((lane >> 4) << 3),
                         wn * 64 + 3 * 16 + (lane & 7) + ((lane >> 4) << 3)};
    const int bbit = (lane >> 3) & 1;

    int stage = 0;
    for (int kt = 0; kt < KT; ++kt) {
        asm volatile("cp.async.wait_group 1;\n" ::: "memory");
        __syncthreads();
        // refill the stage freed at kt-1 (all warps passed the barrier => done reading)
        if (kt + 2 < KT) {
            int st = stage + 2; if (st >= NSTAGE) st -= NSTAGE;
            load_stage(kt + 2, st);
        } else {
            asm volatile("cp.async.commit_group;\n" ::: "memory");
        }

        const uint32_t sa = smbase + stage * STAGE_BYTES;
        const uint32_t sb = sa + A_BYTES;

        #pragma unroll
        for (int ks = 0; ks < 4; ++ks) {        // BK/16
            unsigned af[4][4], bf[4][4];
            #pragma unroll
            for (int mi = 0; mi < 4; ++mi) {
                const int ch = ks * 2 + abit;
                ldsm4(af[mi], sa + arow[mi] * 128 + ((ch ^ (arow[mi] & 7)) << 4));
            }
            #pragma unroll
            for (int nj = 0; nj < 4; ++nj) {
                const int ch = ks * 2 + bbit;
                ldsm4(bf[nj], sb + brow[nj] * 128 + ((ch ^ (brow[nj] & 7)) << 4));
            }
            #pragma unroll
            for (int mi = 0; mi < 4; ++mi)
                #pragma unroll
                for (int ni = 0; ni < 8; ++ni)
                    mma_bf16(acc[mi][ni],
                             af[mi][0], af[mi][1], af[mi][2], af[mi][3],
                             bf[ni >> 1][(ni & 1) * 2], bf[ni >> 1][(ni & 1) * 2 + 1]);
        }
        if (++stage == NSTAGE) stage = 0;
    }

    // epilogue: out = (4*s_x*s_w)*acc + 4*b ; .cs stores protect L2 operand set
    const float alpha = 4.0f * (g_absmax[0] / 127.0f) * (g_absmax[1] / 127.0f);

    #pragma unroll
    for (int mi = 0; mi < 4; ++mi) {
        const int r0 = bm0 + wm * 64 + mi * 16 + (lane >> 2);
        #pragma unroll
        for (int ni = 0; ni < 8; ++ni) {
            const int c0 = bn0 + wn * 64 + ni * 8 + (lane & 3) * 2;
            const float b0v = 4.0f * bias[c0];
            const float b1v = 4.0f * bias[c0 + 1];
            float2 o0 = make_float2(alpha * acc[mi][ni][0] + b0v,
                                    alpha * acc[mi][ni][1] + b1v);
            float2 o1 = make_float2(alpha * acc[mi][ni][2] + b0v,
                                    alpha * acc[mi][ni][3] + b1v);
            __stcs((float2*)(C + (size_t)r0 * N_DIM + c0), o0);
            __stcs((float2*)(C + (size_t)(r0 + 8) * N_DIM + c0), o1);
        }
    }
}

// ---------------- launch ----------------
extern "C" void kernel_launch(void* const* d_in, const int* in_sizes, int n_in,
                              void* d_out, int out_size) {
    const float* x = (const float*)d_in[0];
    const float* W = (const float*)d_in[1];
    const float* b = (const float*)d_in[2];
    float* out = (float*)d_out;

    const int n4x = (M_DIM * K_DIM) / 4;
    const int n4w = (N_DIM * K_DIM) / 4;
    const int n8x = (M_DIM * K_DIM) / 8;
    const int n8w = (N_DIM * K_DIM) / 8;

    init_kernel<<<1, 32>>>();
    absmax_fused_kernel<<<AMAX_BX + AMAX_BW, 256>>>((const float4*)x, n4x,
                                                    (const float4*)W, n4w);
    const int qbx = (n8x + 255) / 256;
    const int qbw = (n8w + 255) / 256;
    quant_fused_kernel<<<qbx + qbw, 256>>>((const float4*)x, n8x, qbx,
                                           (const float4*)W, n8w);

    static bool attr_set = false;
    if (!attr_set) {
        cudaFuncSetAttribute(gemm_kernel,
                             cudaFuncAttributeMaxDynamicSharedMemorySize, SMEM_DYN);
        attr_set = true;
    }
    dim3 grid(N_DIM / BN, M_DIM / BM);  // (32, 64): x-fast over N for L2 reuse
    gemm_kernel<<<grid, NTHREADS, SMEM_DYN>>>(out, b);
}

// round 17
// speedup vs baseline: 1.1205x; 1.0019x over previous
#include <cuda_runtime.h>
#include <cuda_bf16.h>
#include <cstdint>

#define M_DIM 8192
#define N_DIM 4096
#define K_DIM 4096

// ---------------- scratch (no allocations allowed) ----------------
__device__ float g_absmax[2];                         // [0]=x, [1]=W
__device__ __nv_bfloat16 g_qx[(size_t)M_DIM * K_DIM]; // 64 MB
__device__ __nv_bfloat16 g_qw[(size_t)N_DIM * K_DIM]; // 32 MB

// ---------------- init ----------------
__global__ void init_kernel() {
    if (threadIdx.x < 2) g_absmax[threadIdx.x] = 0.0f;
}

// ---------------- fused absmax: blocks [0,bx) -> x, rest -> w ----------------
#define AMAX_BX 6144
#define AMAX_BW 3072
__global__ void absmax_fused_kernel(const float4* __restrict__ px, int n4x,
                                    const float4* __restrict__ pw, int n4w) {
    const int isw  = (blockIdx.x >= AMAX_BX);
    const float4* __restrict__ p = isw ? pw : px;
    const int n4      = isw ? n4w : n4x;
    const int blk     = isw ? (blockIdx.x - AMAX_BX) : blockIdx.x;
    const int nblk    = isw ? AMAX_BW : AMAX_BX;
    const int stride  = nblk * blockDim.x;

    float m = 0.0f;
    int i = blk * blockDim.x + threadIdx.x;
    for (; i + 3 * stride < n4; i += 4 * stride) {
        float4 v0 = __ldcs(p + i);               // streaming: single-use data
        float4 v1 = __ldcs(p + i + stride);
        float4 v2 = __ldcs(p + i + 2 * stride);
        float4 v3 = __ldcs(p + i + 3 * stride);
        float a = fmaxf(fmaxf(fabsf(v0.x), fabsf(v0.y)), fmaxf(fabsf(v0.z), fabsf(v0.w)));
        float b = fmaxf(fmaxf(fabsf(v1.x), fabsf(v1.y)), fmaxf(fabsf(v1.z), fabsf(v1.w)));
        float c = fmaxf(fmaxf(fabsf(v2.x), fabsf(v2.y)), fmaxf(fabsf(v2.z), fabsf(v2.w)));
        float d = fmaxf(fmaxf(fabsf(v3.x), fabsf(v3.y)), fmaxf(fabsf(v3.z), fabsf(v3.w)));
        m = fmaxf(m, fmaxf(fmaxf(a, b), fmaxf(c, d)));
    }
    for (; i < n4; i += stride) {
        float4 v = __ldcs(p + i);
        m = fmaxf(m, fmaxf(fmaxf(fabsf(v.x), fabsf(v.y)), fmaxf(fabsf(v.z), fabsf(v.w))));
    }
    #pragma unroll
    for (int o = 16; o; o >>= 1) m = fmaxf(m, __shfl_xor_sync(0xFFFFFFFFu, m, o));
    __shared__ float sm[32];
    if ((threadIdx.x & 31) == 0) sm[threadIdx.x >> 5] = m;
    __syncthreads();
    if (threadIdx.x < 32) {
        m = (threadIdx.x < (blockDim.x >> 5)) ? sm[threadIdx.x] : 0.0f;
        #pragma unroll
        for (int o = 16; o; o >>= 1) m = fmaxf(m, __shfl_xor_sync(0xFFFFFFFFu, m, o));
        if (threadIdx.x == 0)
            atomicMax((unsigned int*)&g_absmax[isw], __float_as_uint(m));
    }
}

// ---------------- fused quantize: blocks [0,bx) -> x, rest -> w ----------------
__device__ __forceinline__ uint32_t qpack2(float a, float b, float si, float lo) {
    float q0 = fminf(fmaxf(rintf(a * si), lo), 127.0f);
    float q1 = fminf(fmaxf(rintf(b * si), lo), 127.0f);
    __nv_bfloat162 h = __floats2bfloat162_rn(q0, q1);
    return *(uint32_t*)&h;
}

__global__ void quant_fused_kernel(const float4* __restrict__ xin, int n8x, int bx,
                                   const float4* __restrict__ win, int n8w) {
    const int isw = (blockIdx.x >= bx);
    const float4* __restrict__ in = isw ? win : xin;
    const int n8  = isw ? n8w : n8x;
    const float lo = isw ? -127.0f : -128.0f;
    const int i = (isw ? (blockIdx.x - bx) : blockIdx.x) * blockDim.x + threadIdx.x;
    if (i >= n8) return;
    const float si = 127.0f / g_absmax[isw];   // reciprocal once; no per-elem FDIV
    float4 v0 = __ldcs(in + i * 2 + 0);        // streaming: inputs dead after this
    float4 v1 = __ldcs(in + i * 2 + 1);
    uint4 o;
    o.x = qpack2(v0.x, v0.y, si, lo);
    o.y = qpack2(v0.z, v0.w, si, lo);
    o.z = qpack2(v1.x, v1.y, si, lo);
    o.w = qpack2(v1.z, v1.w, si, lo);
    // device-side symbol binding (round-7 lesson); default store policy keeps
    // qx/qw in L2 — the GEMM re-reads them immediately.
    if (isw) ((uint4*)g_qw)[i] = o;
    else     ((uint4*)g_qx)[i] = o;
}

// ---------------- GEMM: C[M,N] = qx[M,K] * qw[N,K]^T ----------------
// 128x128 CTA tile, 128 threads: 4 warps of 64x64 tiles. 3-stage ring,
// 96 KB smem -> 2 CTAs/SM. Loop order wait -> sync -> load -> compute:
// the barrier AFTER the wait publishes all threads' cp.async writes
// (wait_group is per-thread; rounds 15/16 NaN came from reordering this).
#define BM 128
#define BN 128
#define BK 64          // 64 bf16 = 128 bytes per row
#define NTHREADS 128
#define NSTAGE 3
#define KT (K_DIM / BK)            // 64
#define A_BYTES (BM * 128)         // 16 KB
#define B_BYTES (BN * 128)         // 16 KB
#define STAGE_BYTES (A_BYTES + B_BYTES)        // 32 KB
#define SMEM_DYN (NSTAGE * STAGE_BYTES + 128)  // 96 KB + pad

__device__ __forceinline__ unsigned smem_u32(const void* p) {
    return (unsigned)__cvta_generic_to_shared(p);
}

__device__ __forceinline__ void ldsm4(unsigned r[4], unsigned addr) {
    asm volatile("ldmatrix.sync.aligned.m8n8.x4.shared.b16 {%0,%1,%2,%3}, [%4];"
                 : "=r"(r[0]), "=r"(r[1]), "=r"(r[2]), "=r"(r[3])
                 : "r"(addr));
}

__device__ __forceinline__ void mma_bf16(float c[4],
                                         unsigned a0, unsigned a1, unsigned a2, unsigned a3,
                                         unsigned b0, unsigned b1) {
    asm volatile(
        "mma.sync.aligned.m16n8k16.row.col.f32.bf16.bf16.f32 "
        "{%0,%1,%2,%3}, {%4,%5,%6,%7}, {%8,%9}, {%0,%1,%2,%3};"
        : "+f"(c[0]), "+f"(c[1]), "+f"(c[2]), "+f"(c[3])
        : "r"(a0), "r"(a1), "r"(a2), "r"(a3), "r"(b0), "r"(b1));
}

__global__ __launch_bounds__(NTHREADS, 2) void gemm_kernel(float* __restrict__ C,
                                                           const float* __restrict__ bias) {
    extern __shared__ __align__(128) uint8_t dynsmem[];
    uint32_t smbase = smem_u32(dynsmem);
    smbase = (smbase + 127u) & ~127u;

    const int tid  = threadIdx.x;
    const int lane = tid & 31;
    const int warp = tid >> 5;
    const int wm   = warp >> 1;   // 0..1  (64 rows)
    const int wn   = warp & 1;    // 0..1  (64 cols)
    const int bm0  = blockIdx.y * BM;
    const int bn0  = blockIdx.x * BN;

    const __nv_bfloat16* gA = g_qx + (size_t)bm0 * K_DIM;
    const __nv_bfloat16* gB = g_qw + (size_t)bn0 * K_DIM;

    float acc[4][8][4];
    #pragma unroll
    for (int mi = 0; mi < 4; ++mi)
        #pragma unroll
        for (int ni = 0; ni < 8; ++ni)
            #pragma unroll
            for (int r = 0; r < 4; ++r) acc[mi][ni][r] = 0.0f;

    // stage loader: A = 1024 chunks (8/thread), B = 1024 chunks (8/thread)
    auto load_stage = [&](int kt, int stage) {
        const uint32_t sa = smbase + stage * STAGE_BYTES;
        const uint32_t sb = sa + A_BYTES;
        const int k0 = kt * BK;
        #pragma unroll
        for (int i = 0; i < 8; ++i) {
            const int id  = tid + i * NTHREADS;
            const int row = id >> 3, ch = id & 7;
            const uint32_t off = row * 128 + ((ch ^ (row & 7)) << 4);
            const void* srcA = gA + (size_t)row * K_DIM + k0 + ch * 8;
            asm volatile("cp.async.cg.shared.global [%0], [%1], 16;\n"
                         :: "r"(sa + off), "l"(srcA));
            const void* srcB = gB + (size_t)row * K_DIM + k0 + ch * 8;
            asm volatile("cp.async.cg.shared.global [%0], [%1], 16;\n"
                         :: "r"(sb + off), "l"(srcB));
        }
        asm volatile("cp.async.commit_group;\n" ::: "memory");
    };

    load_stage(0, 0);
    load_stage(1, 1);

    // fragment address components
    const int arow[4] = {wm * 64 + 0 * 16 + (lane & 15), wm * 64 + 1 * 16 + (lane & 15),
                         wm * 64 + 2 * 16 + (lane & 15), wm * 64 + 3 * 16 + (lane & 15)};
    const int abit = lane >> 4;
    const int brow[4] = {wn * 64 + 0 * 16 + (lane & 7) + ((lane >> 4) << 3),
                         wn * 64 + 1 * 16 + (lane & 7) + ((lane >> 4) << 3),
                         wn * 64 + 2 * 16 + (lane & 7) + ((lane >> 4) << 3),
                         wn * 64 + 3 * 16 + (lane & 7) + ((lane >> 4) << 3)};
    const int bbit = (lane >> 3) & 1;

    int stage = 0;
    for (int kt = 0; kt < KT; ++kt) {
        asm volatile("cp.async.wait_group 1;\n" ::: "memory");  // stage kt data done (this thread)
        __syncthreads();                                        // publish ALL threads' writes
        // refill the stage freed at kt-1 (barrier also proves it was consumed)
        if (kt + 2 < KT) {
            int st = stage + 2; if (st >= NSTAGE) st -= NSTAGE;
            load_stage(kt + 2, st);
        } else {
            asm volatile("cp.async.commit_group;\n" ::: "memory");
        }

        const uint32_t sa = smbase + stage * STAGE_BYTES;
        const uint32_t sb = sa + A_BYTES;

        #pragma unroll
        for (int ks = 0; ks < 4; ++ks) {        // BK/16
            unsigned af[4][4], bf[4][4];
            #pragma unroll
            for (int mi = 0; mi < 4; ++mi) {
                const int ch = ks * 2 + abit;
                ldsm4(af[mi], sa + arow[mi] * 128 + ((ch ^ (arow[mi] & 7)) << 4));
            }
            #pragma unroll
            for (int nj = 0; nj < 4; ++nj) {
                const int ch = ks * 2 + bbit;
                ldsm4(bf[nj], sb + brow[nj] * 128 + ((ch ^ (brow[nj] & 7)) << 4));
            }
            #pragma unroll
            for (int mi = 0; mi < 4; ++mi)
                #pragma unroll
                for (int ni = 0; ni < 8; ++ni)
                    mma_bf16(acc[mi][ni],
                             af[mi][0], af[mi][1], af[mi][2], af[mi][3],
                             bf[ni >> 1][(ni & 1) * 2], bf[ni >> 1][(ni & 1) * 2 + 1]);
        }
        if (++stage == NSTAGE) stage = 0;
    }

    // epilogue: out = (4*s_x*s_w)*acc + 4*b ; .cs stores protect L2 operand set
    const float alpha = 4.0f * (g_absmax[0] / 127.0f) * (g_absmax[1] / 127.0f);

    #pragma unroll
    for (int mi = 0; mi < 4; ++mi) {
        const int r0 = bm0 + wm * 64 + mi * 16 + (lane >> 2);
        #pragma unroll
        for (int ni = 0; ni < 8; ++ni) {
            const int c0 = bn0 + wn * 64 + ni * 8 + (lane & 3) * 2;
            const float b0v = 4.0f * bias[c0];
            const float b1v = 4.0f * bias[c0 + 1];
            float2 o0 = make_float2(alpha * acc[mi][ni][0] + b0v,
                                    alpha * acc[mi][ni][1] + b1v);
            float2 o1 = make_float2(alpha * acc[mi][ni][2] + b0v,
                                    alpha * acc[mi][ni][3] + b1v);
            __stcs((float2*)(C + (size_t)r0 * N_DIM + c0), o0);
            __stcs((float2*)(C + (size_t)(r0 + 8) * N_DIM + c0), o1);
        }
    }
}

// ---------------- launch ----------------
extern "C" void kernel_launch(void* const* d_in, const int* in_sizes, int n_in,
                              void* d_out, int out_size) {
    const float* x = (const float*)d_in[0];
    const float* W = (const float*)d_in[1];
    const float* b = (const float*)d_in[2];
    float* out = (float*)d_out;

    const int n4x = (M_DIM * K_DIM) / 4;
    const int n4w = (N_DIM * K_DIM) / 4;
    const int n8x = (M_DIM * K_DIM) / 8;
    const int n8w = (N_DIM * K_DIM) / 8;

    init_kernel<<<1, 32>>>();
    absmax_fused_kernel<<<AMAX_BX + AMAX_BW, 256>>>((const float4*)x, n4x,
                                                    (const float4*)W, n4w);
    const int qbx = (n8x + 255) / 256;
    const int qbw = (n8w + 255) / 256;
    quant_fused_kernel<<<qbx + qbw, 256>>>((const float4*)x, n8x, qbx,
                                           (const float4*)W, n8w);

    static bool attr_set = false;
    if (!attr_set) {
        cudaFuncSetAttribute(gemm_kernel,
                             cudaFuncAttributeMaxDynamicSharedMemorySize, SMEM_DYN);
        attr_set = true;
    }
    dim3 grid(N_DIM / BN, M_DIM / BM);  // (32, 64): x-fast over N for L2 reuse
    gemm_kernel<<<grid, NTHREADS, SMEM_DYN>>>(out, b);
}